// round 1
// baseline (speedup 1.0000x reference)
#include <cuda_runtime.h>
#include <math.h>

#define BSZ 4096
#define HD  128
#define TDIM 768

// ---------------- device scratch (no allocs allowed) ----------------
__device__ float g_LN[BSZ * HD];      // normalized logits
__device__ float g_T[BSZ * TDIM];     // normalized teacher
__device__ float g_GH[HD * HD];       // H^T H   (split-K accumulated)
__device__ float g_C[HD * TDIM];      // H^T T   (split-K accumulated)
__device__ float g_denom[BSZ];
__device__ float g_pos[BSZ];
__device__ float g_cnt[BSZ];
__device__ float g_quant;
__device__ float g_ST;                // ||T^T T||_F^2

// ---------------- zero accumulators each launch ----------------
__global__ void k_zero() {
    int i = blockIdx.x * 256 + threadIdx.x;
    if (i < HD * HD)  g_GH[i] = 0.f;
    if (i < HD * TDIM) g_C[i] = 0.f;
    if (i < BSZ) { g_denom[i] = 0.f; g_pos[i] = 0.f; g_cnt[i] = 0.f; }
    if (i == 0) { g_quant = 0.f; g_ST = 0.f; }
}

// ---------------- normalize logits + quant loss partial ----------------
__global__ void k_norm_logits(const float* __restrict__ x) {
    int row = blockIdx.x;
    int t = threadIdx.x;                 // 128 threads
    float v = x[row * HD + t];
    float ss = v * v;
    float q = fabsf(fabsf(v) - 1.0f);
    #pragma unroll
    for (int o = 16; o >= 1; o >>= 1) {
        ss += __shfl_xor_sync(0xffffffffu, ss, o);
        q  += __shfl_xor_sync(0xffffffffu, q, o);
    }
    __shared__ float sred[4], qred[4];
    __shared__ float sinv;
    int w = t >> 5, l = t & 31;
    if (l == 0) { sred[w] = ss; qred[w] = q; }
    __syncthreads();
    if (t == 0) {
        float tot = sred[0] + sred[1] + sred[2] + sred[3];
        float qt  = qred[0] + qred[1] + qred[2] + qred[3];
        atomicAdd(&g_quant, qt);
        sinv = 1.0f / fmaxf(sqrtf(tot), 1e-12f);
    }
    __syncthreads();
    g_LN[row * HD + t] = v * sinv;
}

// ---------------- normalize teacher ----------------
__global__ void k_norm_teacher(const float* __restrict__ x) {
    int row = blockIdx.x;
    int t = threadIdx.x;                 // 256 threads
    float v0 = x[row * TDIM + t];
    float v1 = x[row * TDIM + 256 + t];
    float v2 = x[row * TDIM + 512 + t];
    float ss = v0 * v0 + v1 * v1 + v2 * v2;
    #pragma unroll
    for (int o = 16; o >= 1; o >>= 1) ss += __shfl_xor_sync(0xffffffffu, ss, o);
    __shared__ float sred[8];
    __shared__ float sinv;
    if ((t & 31) == 0) sred[t >> 5] = ss;
    __syncthreads();
    if (t == 0) {
        float tot = 0.f;
        #pragma unroll
        for (int i = 0; i < 8; i++) tot += sred[i];
        sinv = 1.0f / fmaxf(sqrtf(tot), 1e-12f);
    }
    __syncthreads();
    g_T[row * TDIM + t]       = v0 * sinv;
    g_T[row * TDIM + 256 + t] = v1 * sinv;
    g_T[row * TDIM + 512 + t] = v2 * sinv;
}

// ---------------- generic A^T B tile GEMM, split-K, atomic accumulate ----------------
// bsel: 0 -> B operand = A (same matrix), 1 -> B operand = g_T
// osel: 0 -> out = g_GH (ldo=HD), 1 -> out = g_C (ldo=TDIM)
__global__ void __launch_bounds__(256) k_atb(const float* __restrict__ A, int lda,
                                             int bsel, int ldb, int kPer,
                                             int osel, int ldo) {
    __shared__ float As[32][68];
    __shared__ float Bs[32][68];
    const float* Bm = bsel ? g_T : A;
    float* out = osel ? g_C : g_GH;
    int m0 = blockIdx.x * 64, n0 = blockIdx.y * 64;
    int kBeg = blockIdx.z * kPer, kEnd = kBeg + kPer;
    int tid = threadIdx.x;
    int tx = tid & 15, ty = tid >> 4;
    float acc[4][4] = {};
    for (int k0 = kBeg; k0 < kEnd; k0 += 32) {
        __syncthreads();
        #pragma unroll
        for (int s = 0; s < 2; s++) {
            int i = tid + s * 256;
            int r = i >> 4, c4 = (i & 15) * 4;
            *(float4*)&As[r][c4] = *(const float4*)&A[(k0 + r) * lda + m0 + c4];
            *(float4*)&Bs[r][c4] = *(const float4*)&Bm[(k0 + r) * ldb + n0 + c4];
        }
        __syncthreads();
        #pragma unroll
        for (int kk = 0; kk < 32; kk++) {
            float4 a4 = *(const float4*)&As[kk][ty * 4];
            float4 b4 = *(const float4*)&Bs[kk][tx * 4];
            float av[4] = {a4.x, a4.y, a4.z, a4.w};
            float bv[4] = {b4.x, b4.y, b4.z, b4.w};
            #pragma unroll
            for (int ii = 0; ii < 4; ii++)
                #pragma unroll
                for (int jj = 0; jj < 4; jj++)
                    acc[ii][jj] += av[ii] * bv[jj];
        }
    }
    #pragma unroll
    for (int ii = 0; ii < 4; ii++)
        #pragma unroll
        for (int jj = 0; jj < 4; jj++)
            atomicAdd(&out[(m0 + ty * 4 + ii) * ldo + (n0 + tx * 4 + jj)], acc[ii][jj]);
}

// ---------------- ||T^T T||_F^2 directly (no materialization, full-K tiles) ----------------
__global__ void __launch_bounds__(256) k_tt_frob() {
    __shared__ float As[32][68];
    __shared__ float Bs[32][68];
    int m0 = blockIdx.x * 64, n0 = blockIdx.y * 64;
    int tid = threadIdx.x;
    int tx = tid & 15, ty = tid >> 4;
    float acc[4][4] = {};
    for (int k0 = 0; k0 < BSZ; k0 += 32) {
        __syncthreads();
        #pragma unroll
        for (int s = 0; s < 2; s++) {
            int i = tid + s * 256;
            int r = i >> 4, c4 = (i & 15) * 4;
            *(float4*)&As[r][c4] = *(const float4*)&g_T[(k0 + r) * TDIM + m0 + c4];
            *(float4*)&Bs[r][c4] = *(const float4*)&g_T[(k0 + r) * TDIM + n0 + c4];
        }
        __syncthreads();
        #pragma unroll
        for (int kk = 0; kk < 32; kk++) {
            float4 a4 = *(const float4*)&As[kk][ty * 4];
            float4 b4 = *(const float4*)&Bs[kk][tx * 4];
            float av[4] = {a4.x, a4.y, a4.z, a4.w};
            float bv[4] = {b4.x, b4.y, b4.z, b4.w};
            #pragma unroll
            for (int ii = 0; ii < 4; ii++)
                #pragma unroll
                for (int jj = 0; jj < 4; jj++)
                    acc[ii][jj] += av[ii] * bv[jj];
        }
    }
    float s = 0.f;
    #pragma unroll
    for (int ii = 0; ii < 4; ii++)
        #pragma unroll
        for (int jj = 0; jj < 4; jj++) s += acc[ii][jj] * acc[ii][jj];
    #pragma unroll
    for (int o = 16; o >= 1; o >>= 1) s += __shfl_xor_sync(0xffffffffu, s, o);
    __shared__ float red[8];
    if ((tid & 31) == 0) red[tid >> 5] = s;
    __syncthreads();
    if (tid == 0) {
        float t = 0.f;
        #pragma unroll
        for (int i = 0; i < 8; i++) t += red[i];
        atomicAdd(&g_ST, t);
    }
}

// ---------------- contrastive: sim tile -> exp-sum / masked pos-sum ----------------
// Block: 64-row tile x 512-col span (8 chunks of 64). Micro 4x4, strided (step 16).
__global__ void __launch_bounds__(256) k_cont(const int* __restrict__ pmask) {
    __shared__ float4 As4[64][17];
    __shared__ float4 Bs4[64][17];
    int i0 = blockIdx.x * 64;
    int tid = threadIdx.x;
    int tx = tid & 15, ty = tid >> 4;
    float dpart[4] = {0.f, 0.f, 0.f, 0.f};
    float ppart[4] = {0.f, 0.f, 0.f, 0.f};
    float cpart[4] = {0.f, 0.f, 0.f, 0.f};
    const float4* LN4 = (const float4*)g_LN;   // row stride = 32 float4

    for (int cc = 0; cc < 8; cc++) {
        int j0 = blockIdx.y * 512 + cc * 64;
        float acc[4][4] = {};
        #pragma unroll
        for (int kh = 0; kh < 2; kh++) {
            __syncthreads();
            #pragma unroll
            for (int s = 0; s < 4; s++) {
                int idx = tid + s * 256;
                int r = idx >> 4, c = idx & 15;
                As4[r][c] = LN4[(i0 + r) * 32 + kh * 16 + c];
                Bs4[r][c] = LN4[(j0 + r) * 32 + kh * 16 + c];
            }
            __syncthreads();
            #pragma unroll
            for (int k4 = 0; k4 < 16; k4++) {
                float4 a[4], b[4];
                #pragma unroll
                for (int ii = 0; ii < 4; ii++) a[ii] = As4[ty + 16 * ii][k4];
                #pragma unroll
                for (int jj = 0; jj < 4; jj++) b[jj] = Bs4[tx + 16 * jj][k4];
                #pragma unroll
                for (int ii = 0; ii < 4; ii++)
                    #pragma unroll
                    for (int jj = 0; jj < 4; jj++) {
                        acc[ii][jj] += a[ii].x * b[jj].x;
                        acc[ii][jj] += a[ii].y * b[jj].y;
                        acc[ii][jj] += a[ii].z * b[jj].z;
                        acc[ii][jj] += a[ii].w * b[jj].w;
                    }
            }
        }
        // epilogue: exp-sum (excl. diag), masked positive sum + count
        #pragma unroll
        for (int ii = 0; ii < 4; ii++) {
            int gi = i0 + ty + 16 * ii;
            #pragma unroll
            for (int jj = 0; jj < 4; jj++) {
                int gj = j0 + tx + 16 * jj;
                float sv = acc[ii][jj] * 5.0f;           // 1 / TEMPERATURE
                if (gj != gi) dpart[ii] += __expf(sv);
                if (pmask[gi * BSZ + gj] != 0) { ppart[ii] += sv; cpart[ii] += 1.0f; }
            }
        }
    }
    // reduce across tx (groups of 16 lanes)
    #pragma unroll
    for (int ii = 0; ii < 4; ii++) {
        #pragma unroll
        for (int o = 8; o >= 1; o >>= 1) {
            dpart[ii] += __shfl_down_sync(0xffffffffu, dpart[ii], o, 16);
            ppart[ii] += __shfl_down_sync(0xffffffffu, ppart[ii], o, 16);
            cpart[ii] += __shfl_down_sync(0xffffffffu, cpart[ii], o, 16);
        }
    }
    if (tx == 0) {
        #pragma unroll
        for (int ii = 0; ii < 4; ii++) {
            int gi = i0 + ty + 16 * ii;
            atomicAdd(&g_denom[gi], dpart[ii]);
            atomicAdd(&g_pos[gi],   ppart[ii]);
            atomicAdd(&g_cnt[gi],   cpart[ii]);
        }
    }
}

// ---------------- final combine ----------------
__global__ void k_combine(float* __restrict__ out) {
    int tid = threadIdx.x;               // 256 threads
    float cont = 0.f, sh = 0.f, sc = 0.f;
    for (int i = tid; i < BSZ; i += 256)
        cont += logf(g_denom[i]) - g_pos[i] / fmaxf(g_cnt[i], 1.0f);
    for (int i = tid; i < HD * HD; i += 256) { float v = g_GH[i]; sh += v * v; }
    for (int i = tid; i < HD * TDIM; i += 256) { float v = g_C[i]; sc += v * v; }
    #pragma unroll
    for (int o = 16; o >= 1; o >>= 1) {
        cont += __shfl_xor_sync(0xffffffffu, cont, o);
        sh   += __shfl_xor_sync(0xffffffffu, sh, o);
        sc   += __shfl_xor_sync(0xffffffffu, sc, o);
    }
    __shared__ float r0[8], r1[8], r2[8];
    if ((tid & 31) == 0) { int w = tid >> 5; r0[w] = cont; r1[w] = sh; r2[w] = sc; }
    __syncthreads();
    if (tid == 0) {
        float cT = 0.f, shT = 0.f, scT = 0.f;
        #pragma unroll
        for (int i = 0; i < 8; i++) { cT += r0[i]; shT += r1[i]; scT += r2[i]; }
        float B2 = (float)BSZ * (float)BSZ;
        float distill = (shT / (128.f * 128.f) - 2.f * scT / 128.f + g_ST) / B2;
        float quant = g_quant / ((float)BSZ * (float)HD);
        out[0] = cT / (float)BSZ + 0.5f * distill + 0.01f * quant;
    }
}

// ---------------- launch ----------------
extern "C" void kernel_launch(void* const* d_in, const int* in_sizes, int n_in,
                              void* d_out, int out_size) {
    const float* logits = (const float*)d_in[0];
    const float* hash   = (const float*)d_in[1];
    const float* teach  = (const float*)d_in[2];
    const int*   pmask  = (const int*)d_in[3];
    float* out = (float*)d_out;

    k_zero<<<384, 256>>>();
    k_norm_logits<<<BSZ, 128>>>(logits);
    k_norm_teacher<<<BSZ, 256>>>(teach);
    // G_H = H^T H : 128x128, split-K 8
    k_atb<<<dim3(2, 2, 8), 256>>>(hash, HD, /*bsel=*/0, HD, /*kPer=*/512, /*osel=*/0, HD);
    // C = H^T T : 128x768, split-K 4
    k_atb<<<dim3(2, 12, 4), 256>>>(hash, HD, /*bsel=*/1, TDIM, /*kPer=*/1024, /*osel=*/1, TDIM);
    // ||T^T T||_F^2 : 768x768 tiles, full K
    k_tt_frob<<<dim3(12, 12), 256>>>();
    // contrastive over 4096x4096 sim
    k_cont<<<dim3(64, 8), 256>>>(pmask);
    k_combine<<<1, 256>>>(out);
}

// round 2
// speedup vs baseline: 1.2472x; 1.2472x over previous
#include <cuda_runtime.h>
#include <math.h>

#define BSZ 4096
#define HD  128
#define TDIM 768

typedef unsigned long long u64;

__device__ __forceinline__ void fma2(u64 &d, u64 a, u64 b) {
    asm("fma.rn.f32x2 %0, %1, %2, %0;" : "+l"(d) : "l"(a), "l"(b));
}
__device__ __forceinline__ float upsum(u64 v) {
    float lo, hi;
    asm("mov.b64 {%0,%1}, %2;" : "=f"(lo), "=f"(hi) : "l"(v));
    return lo + hi;
}
union F4U { float4 f; u64 u[2]; };

// ---------------- device scratch ----------------
__device__ float g_LN[BSZ * HD];        // normalized logits  [B][128]
__device__ float g_T [BSZ * TDIM];      // normalized teacher [B][768]
__device__ float g_Ht[HD * BSZ];        // hash^T   [128][4096]
__device__ float g_Tt[TDIM * BSZ];      // teacher^T [768][4096]
__device__ float g_GH[HD * HD];         // H^T H
__device__ float g_C [HD * TDIM];       // H^T T
__device__ float g_TT[TDIM * TDIM];     // T^T T (upper triangle valid)
__device__ float g_denom[BSZ];
__device__ float g_pos[BSZ];
__device__ float g_cnt[BSZ];
__device__ float g_quant;
__device__ float g_ST;                  // distill (unweighted) accumulator

// ---------------- zero accumulators ----------------
__global__ void k_zero() {
    int i = blockIdx.x * 256 + threadIdx.x;
    int n = gridDim.x * 256;
    for (int j = i; j < TDIM * TDIM; j += n) g_TT[j] = 0.f;
    for (int j = i; j < HD * TDIM;  j += n) g_C[j]  = 0.f;
    if (i < HD * HD) g_GH[i] = 0.f;
    if (i < BSZ) { g_denom[i] = 0.f; g_pos[i] = 0.f; g_cnt[i] = 0.f; }
    if (i == 0) { g_quant = 0.f; g_ST = 0.f; }
}

// ---------------- normalize logits + quant partial ----------------
__global__ void k_norm_logits(const float* __restrict__ x) {
    int row = blockIdx.x;
    int t = threadIdx.x;                 // 128 threads
    float v = x[row * HD + t];
    float ss = v * v;
    float q = fabsf(fabsf(v) - 1.0f);
    #pragma unroll
    for (int o = 16; o >= 1; o >>= 1) {
        ss += __shfl_xor_sync(0xffffffffu, ss, o);
        q  += __shfl_xor_sync(0xffffffffu, q, o);
    }
    __shared__ float sred[4], qred[4];
    __shared__ float sinv;
    int w = t >> 5, l = t & 31;
    if (l == 0) { sred[w] = ss; qred[w] = q; }
    __syncthreads();
    if (t == 0) {
        float tot = sred[0] + sred[1] + sred[2] + sred[3];
        float qt  = qred[0] + qred[1] + qred[2] + qred[3];
        atomicAdd(&g_quant, qt);
        sinv = 1.0f / fmaxf(sqrtf(tot), 1e-12f);
    }
    __syncthreads();
    g_LN[row * HD + t] = v * sinv;
}

// ---------------- normalize teacher ----------------
__global__ void k_norm_teacher(const float* __restrict__ x) {
    int row = blockIdx.x;
    int t = threadIdx.x;                 // 256 threads
    float v0 = x[row * TDIM + t];
    float v1 = x[row * TDIM + 256 + t];
    float v2 = x[row * TDIM + 512 + t];
    float ss = v0 * v0 + v1 * v1 + v2 * v2;
    #pragma unroll
    for (int o = 16; o >= 1; o >>= 1) ss += __shfl_xor_sync(0xffffffffu, ss, o);
    __shared__ float sred[8];
    __shared__ float sinv;
    if ((t & 31) == 0) sred[t >> 5] = ss;
    __syncthreads();
    if (t == 0) {
        float tot = 0.f;
        #pragma unroll
        for (int i = 0; i < 8; i++) tot += sred[i];
        sinv = 1.0f / fmaxf(sqrtf(tot), 1e-12f);
    }
    __syncthreads();
    g_T[row * TDIM + t]       = v0 * sinv;
    g_T[row * TDIM + 256 + t] = v1 * sinv;
    g_T[row * TDIM + 512 + t] = v2 * sinv;
}

// ---------------- tiled transpose: dst[C][R] = src[R][C]^T ----------------
__global__ void k_transpose(const float* __restrict__ src, float* __restrict__ dst,
                            int R, int C) {
    __shared__ float t[32][33];
    int c0 = blockIdx.x * 32, r0 = blockIdx.y * 32;
    int x = threadIdx.x, y = threadIdx.y;   // block (32, 8)
    #pragma unroll
    for (int i = 0; i < 32; i += 8) t[y + i][x] = src[(r0 + y + i) * C + c0 + x];
    __syncthreads();
    #pragma unroll
    for (int i = 0; i < 32; i += 8) dst[(c0 + y + i) * R + r0 + x] = t[x][y + i];
}

// ---------------- k-packed A*B^T GEMM (both operands [rows][4096], k-contig) ----
// out[(m)*ldo + n] += sum_k A[m][k]*B[n][k], 64x64 tile, 4x4 micro, FFMA2.
__global__ void __launch_bounds__(256) k_gemm(const float* __restrict__ A,
                                              const float* __restrict__ Bm,
                                              float* __restrict__ out, int ldo,
                                              int kPer) {
    __shared__ float4 As4[64][17];
    __shared__ float4 Bs4[64][17];
    int m0 = blockIdx.x * 64, n0 = blockIdx.y * 64;
    int kBeg = blockIdx.z * kPer;
    int tid = threadIdx.x, tx = tid & 15, ty = tid >> 4;
    const float4* A4 = (const float4*)A;    // row stride 1024 float4
    const float4* B4 = (const float4*)Bm;
    u64 acc[4][4] = {};
    for (int k0 = kBeg; k0 < kBeg + kPer; k0 += 64) {
        __syncthreads();
        #pragma unroll
        for (int s = 0; s < 4; s++) {
            int idx = tid + s * 256;
            int r = idx >> 4, c = idx & 15;
            As4[r][c] = A4[(m0 + r) * 1024 + (k0 >> 2) + c];
            Bs4[r][c] = B4[(n0 + r) * 1024 + (k0 >> 2) + c];
        }
        __syncthreads();
        #pragma unroll
        for (int k4 = 0; k4 < 16; k4++) {
            F4U a[4], b[4];
            #pragma unroll
            for (int ii = 0; ii < 4; ii++) a[ii].f = As4[ty + 16 * ii][k4];
            #pragma unroll
            for (int jj = 0; jj < 4; jj++) b[jj].f = Bs4[tx + 16 * jj][k4];
            #pragma unroll
            for (int ii = 0; ii < 4; ii++)
                #pragma unroll
                for (int jj = 0; jj < 4; jj++) {
                    fma2(acc[ii][jj], a[ii].u[0], b[jj].u[0]);
                    fma2(acc[ii][jj], a[ii].u[1], b[jj].u[1]);
                }
        }
    }
    #pragma unroll
    for (int ii = 0; ii < 4; ii++)
        #pragma unroll
        for (int jj = 0; jj < 4; jj++)
            atomicAdd(&out[(m0 + ty + 16 * ii) * ldo + (n0 + tx + 16 * jj)],
                      upsum(acc[ii][jj]));
}

// ---------------- T^T T upper-triangle tiles only ----------------
__global__ void __launch_bounds__(256) k_gemm_tri(int kPer) {
    __shared__ float4 As4[64][17];
    __shared__ float4 Bs4[64][17];
    // decode upper-triangle tile id (12x12 tiles -> 78)
    int t = blockIdx.x, tm = 0;
    while (t >= 12 - tm) { t -= 12 - tm; tm++; }
    int tn = tm + t;
    int m0 = tm * 64, n0 = tn * 64;
    int kBeg = blockIdx.z * kPer;
    int tid = threadIdx.x, tx = tid & 15, ty = tid >> 4;
    const float4* A4 = (const float4*)g_Tt;
    u64 acc[4][4] = {};
    for (int k0 = kBeg; k0 < kBeg + kPer; k0 += 64) {
        __syncthreads();
        #pragma unroll
        for (int s = 0; s < 4; s++) {
            int idx = tid + s * 256;
            int r = idx >> 4, c = idx & 15;
            As4[r][c] = A4[(m0 + r) * 1024 + (k0 >> 2) + c];
            Bs4[r][c] = A4[(n0 + r) * 1024 + (k0 >> 2) + c];
        }
        __syncthreads();
        #pragma unroll
        for (int k4 = 0; k4 < 16; k4++) {
            F4U a[4], b[4];
            #pragma unroll
            for (int ii = 0; ii < 4; ii++) a[ii].f = As4[ty + 16 * ii][k4];
            #pragma unroll
            for (int jj = 0; jj < 4; jj++) b[jj].f = Bs4[tx + 16 * jj][k4];
            #pragma unroll
            for (int ii = 0; ii < 4; ii++)
                #pragma unroll
                for (int jj = 0; jj < 4; jj++) {
                    fma2(acc[ii][jj], a[ii].u[0], b[jj].u[0]);
                    fma2(acc[ii][jj], a[ii].u[1], b[jj].u[1]);
                }
        }
    }
    #pragma unroll
    for (int ii = 0; ii < 4; ii++)
        #pragma unroll
        for (int jj = 0; jj < 4; jj++)
            atomicAdd(&g_TT[(m0 + ty + 16 * ii) * TDIM + (n0 + tx + 16 * jj)],
                      upsum(acc[ii][jj]));
}

// ---------------- distill square-reduce ----------------
__global__ void k_sq3() {
    int i = blockIdx.x * 256 + threadIdx.x;
    int n = gridDim.x * 256;
    float s = 0.f;
    for (int j = i; j < HD * HD; j += n) {
        float v = g_GH[j]; s += v * v * (1.f / (128.f * 128.f));
    }
    for (int j = i; j < HD * TDIM; j += n) {
        float v = g_C[j]; s -= 2.f * v * v * (1.f / 128.f);
    }
    for (int j = i; j < TDIM * TDIM; j += n) {
        int r = j / TDIM, c = j % TDIM;
        if (c < r) continue;
        float v = g_TT[j];
        s += (c == r) ? v * v : 2.f * v * v;
    }
    #pragma unroll
    for (int o = 16; o >= 1; o >>= 1) s += __shfl_xor_sync(0xffffffffu, s, o);
    __shared__ float red[8];
    if ((threadIdx.x & 31) == 0) red[threadIdx.x >> 5] = s;
    __syncthreads();
    if (threadIdx.x == 0) {
        float tot = 0.f;
        #pragma unroll
        for (int k = 0; k < 8; k++) tot += red[k];
        atomicAdd(&g_ST, tot / ((float)BSZ * (float)BSZ));
    }
}

// ---------------- contrastive: sim tile -> exp-sum / masked pos-sum ----------------
__global__ void __launch_bounds__(256) k_cont(const int* __restrict__ pmask) {
    __shared__ float4 As4[64][17];
    __shared__ float4 Bs4[64][17];
    int i0 = blockIdx.x * 64;
    int tid = threadIdx.x;
    int tx = tid & 15, ty = tid >> 4;
    float dpart[4] = {0.f, 0.f, 0.f, 0.f};
    float ppart[4] = {0.f, 0.f, 0.f, 0.f};
    float cpart[4] = {0.f, 0.f, 0.f, 0.f};
    const float4* LN4 = (const float4*)g_LN;   // row stride = 32 float4

    for (int cc = 0; cc < 8; cc++) {
        int j0 = blockIdx.y * 512 + cc * 64;
        u64 acc[4][4] = {};
        #pragma unroll
        for (int kh = 0; kh < 2; kh++) {
            __syncthreads();
            #pragma unroll
            for (int s = 0; s < 4; s++) {
                int idx = tid + s * 256;
                int r = idx >> 4, c = idx & 15;
                As4[r][c] = LN4[(i0 + r) * 32 + kh * 16 + c];
                Bs4[r][c] = LN4[(j0 + r) * 32 + kh * 16 + c];
            }
            __syncthreads();
            #pragma unroll
            for (int k4 = 0; k4 < 16; k4++) {
                F4U a[4], b[4];
                #pragma unroll
                for (int ii = 0; ii < 4; ii++) a[ii].f = As4[ty + 16 * ii][k4];
                #pragma unroll
                for (int jj = 0; jj < 4; jj++) b[jj].f = Bs4[tx + 16 * jj][k4];
                #pragma unroll
                for (int ii = 0; ii < 4; ii++)
                    #pragma unroll
                    for (int jj = 0; jj < 4; jj++) {
                        fma2(acc[ii][jj], a[ii].u[0], b[jj].u[0]);
                        fma2(acc[ii][jj], a[ii].u[1], b[jj].u[1]);
                    }
            }
        }
        // epilogue: exp-sum (excl. diag), masked positive sum + count
        #pragma unroll
        for (int ii = 0; ii < 4; ii++) {
            int gi = i0 + ty + 16 * ii;
            #pragma unroll
            for (int jj = 0; jj < 4; jj++) {
                int gj = j0 + tx + 16 * jj;
                float sv = upsum(acc[ii][jj]) * 5.0f;     // 1 / TEMPERATURE
                if (gj != gi) dpart[ii] += __expf(sv);
                if (pmask[gi * BSZ + gj] != 0) { ppart[ii] += sv; cpart[ii] += 1.0f; }
            }
        }
    }
    #pragma unroll
    for (int ii = 0; ii < 4; ii++) {
        #pragma unroll
        for (int o = 8; o >= 1; o >>= 1) {
            dpart[ii] += __shfl_down_sync(0xffffffffu, dpart[ii], o, 16);
            ppart[ii] += __shfl_down_sync(0xffffffffu, ppart[ii], o, 16);
            cpart[ii] += __shfl_down_sync(0xffffffffu, cpart[ii], o, 16);
        }
    }
    if (tx == 0) {
        #pragma unroll
        for (int ii = 0; ii < 4; ii++) {
            int gi = i0 + ty + 16 * ii;
            atomicAdd(&g_denom[gi], dpart[ii]);
            atomicAdd(&g_pos[gi],   ppart[ii]);
            atomicAdd(&g_cnt[gi],   cpart[ii]);
        }
    }
}

// ---------------- final combine ----------------
__global__ void k_combine(float* __restrict__ out) {
    int tid = threadIdx.x;               // 256 threads
    float cont = 0.f;
    for (int i = tid; i < BSZ; i += 256)
        cont += logf(g_denom[i]) - g_pos[i] / fmaxf(g_cnt[i], 1.0f);
    #pragma unroll
    for (int o = 16; o >= 1; o >>= 1)
        cont += __shfl_xor_sync(0xffffffffu, cont, o);
    __shared__ float r0[8];
    if ((tid & 31) == 0) r0[tid >> 5] = cont;
    __syncthreads();
    if (tid == 0) {
        float cT = 0.f;
        #pragma unroll
        for (int i = 0; i < 8; i++) cT += r0[i];
        float quant = g_quant / ((float)BSZ * (float)HD);
        out[0] = cT / (float)BSZ + 0.5f * g_ST + 0.01f * quant;
    }
}

// ---------------- launch ----------------
extern "C" void kernel_launch(void* const* d_in, const int* in_sizes, int n_in,
                              void* d_out, int out_size) {
    const float* logits = (const float*)d_in[0];
    const float* hash   = (const float*)d_in[1];
    const float* teach  = (const float*)d_in[2];
    const int*   pmask  = (const int*)d_in[3];
    float* out = (float*)d_out;

    float* p_LN; cudaGetSymbolAddress((void**)&p_LN, g_LN);
    float* p_T;  cudaGetSymbolAddress((void**)&p_T,  g_T);
    float* p_Ht; cudaGetSymbolAddress((void**)&p_Ht, g_Ht);
    float* p_Tt; cudaGetSymbolAddress((void**)&p_Tt, g_Tt);
    float* p_GH; cudaGetSymbolAddress((void**)&p_GH, g_GH);
    float* p_C;  cudaGetSymbolAddress((void**)&p_C,  g_C);

    k_zero<<<512, 256>>>();
    k_norm_logits<<<BSZ, 128>>>(logits);
    k_norm_teacher<<<BSZ, 256>>>(teach);
    // transposes: hash [4096][128] -> Ht [128][4096]; g_T -> Tt [768][4096]
    k_transpose<<<dim3(HD / 32, BSZ / 32), dim3(32, 8)>>>(hash, p_Ht, BSZ, HD);
    k_transpose<<<dim3(TDIM / 32, BSZ / 32), dim3(32, 8)>>>(p_T, p_Tt, BSZ, TDIM);
    // G_H = H^T H : 128x128, split-K 16
    k_gemm<<<dim3(2, 2, 16), 256>>>(p_Ht, p_Ht, p_GH, HD, 256);
    // C = H^T T : 128x768, split-K 8
    k_gemm<<<dim3(2, 12, 8), 256>>>(p_Ht, p_Tt, p_C, TDIM, 512);
    // T^T T upper triangle : 78 tiles, split-K 8
    k_gemm_tri<<<dim3(78, 1, 8), 256>>>(512);
    // distill reduce
    k_sq3<<<512, 256>>>();
    // contrastive over 4096x4096 sim
    k_cont<<<dim3(64, 8), 256>>>(pmask);
    k_combine<<<1, 256>>>(out);
}

// round 3
// speedup vs baseline: 1.6506x; 1.3235x over previous
#include <cuda_runtime.h>
#include <math.h>

#define BSZ 4096
#define HD  128
#define TDIM 768

typedef unsigned long long u64;

__device__ __forceinline__ void fma2(u64 &d, u64 a, u64 b) {
    asm("fma.rn.f32x2 %0, %1, %2, %0;" : "+l"(d) : "l"(a), "l"(b));
}
__device__ __forceinline__ float upsum(u64 v) {
    float lo, hi;
    asm("mov.b64 {%0,%1}, %2;" : "=f"(lo), "=f"(hi) : "l"(v));
    return lo + hi;
}
union F4U { float4 f; u64 u[2]; };

// ---------------- device scratch ----------------
__device__ float g_LN[BSZ * HD];        // normalized logits  [B][128]
__device__ float g_T [BSZ * TDIM];      // normalized teacher [B][768]
__device__ float g_Ht[HD * BSZ];        // hash^T   [128][4096]
__device__ float g_Tt[TDIM * BSZ];      // teacher^T [768][4096]
__device__ float g_GH[HD * HD];         // H^T H
__device__ float g_C [HD * TDIM];       // H^T T
__device__ float g_TT[TDIM * TDIM];     // T^T T (upper triangle valid)
__device__ float g_denom[BSZ];
__device__ float g_pos[BSZ];
__device__ float g_cnt[BSZ];
__device__ float g_quant;
__device__ float g_ST;

// ---------------- zero accumulators ----------------
__global__ void k_zero() {
    int i = blockIdx.x * 256 + threadIdx.x;
    int n = gridDim.x * 256;
    for (int j = i; j < TDIM * TDIM; j += n) g_TT[j] = 0.f;
    for (int j = i; j < HD * TDIM;  j += n) g_C[j]  = 0.f;
    if (i < HD * HD) g_GH[i] = 0.f;
    if (i < BSZ) { g_denom[i] = 0.f; g_pos[i] = 0.f; g_cnt[i] = 0.f; }
    if (i == 0) { g_quant = 0.f; g_ST = 0.f; }
}

// ---------------- normalize logits + quant partial ----------------
__global__ void k_norm_logits(const float* __restrict__ x) {
    int row = blockIdx.x;
    int t = threadIdx.x;                 // 128 threads
    float v = x[row * HD + t];
    float ss = v * v;
    float q = fabsf(fabsf(v) - 1.0f);
    #pragma unroll
    for (int o = 16; o >= 1; o >>= 1) {
        ss += __shfl_xor_sync(0xffffffffu, ss, o);
        q  += __shfl_xor_sync(0xffffffffu, q, o);
    }
    __shared__ float sred[4], qred[4];
    __shared__ float sinv;
    int w = t >> 5, l = t & 31;
    if (l == 0) { sred[w] = ss; qred[w] = q; }
    __syncthreads();
    if (t == 0) {
        float tot = sred[0] + sred[1] + sred[2] + sred[3];
        float qt  = qred[0] + qred[1] + qred[2] + qred[3];
        atomicAdd(&g_quant, qt);
        sinv = 1.0f / fmaxf(sqrtf(tot), 1e-12f);
    }
    __syncthreads();
    g_LN[row * HD + t] = v * sinv;
}

// ---------------- normalize teacher ----------------
__global__ void k_norm_teacher(const float* __restrict__ x) {
    int row = blockIdx.x;
    int t = threadIdx.x;                 // 256 threads
    float v0 = x[row * TDIM + t];
    float v1 = x[row * TDIM + 256 + t];
    float v2 = x[row * TDIM + 512 + t];
    float ss = v0 * v0 + v1 * v1 + v2 * v2;
    #pragma unroll
    for (int o = 16; o >= 1; o >>= 1) ss += __shfl_xor_sync(0xffffffffu, ss, o);
    __shared__ float sred[8];
    __shared__ float sinv;
    if ((t & 31) == 0) sred[t >> 5] = ss;
    __syncthreads();
    if (t == 0) {
        float tot = 0.f;
        #pragma unroll
        for (int i = 0; i < 8; i++) tot += sred[i];
        sinv = 1.0f / fmaxf(sqrtf(tot), 1e-12f);
    }
    __syncthreads();
    g_T[row * TDIM + t]       = v0 * sinv;
    g_T[row * TDIM + 256 + t] = v1 * sinv;
    g_T[row * TDIM + 512 + t] = v2 * sinv;
}

// ---------------- tiled transpose ----------------
__global__ void k_transpose(const float* __restrict__ src, float* __restrict__ dst,
                            int R, int C) {
    __shared__ float t[32][33];
    int c0 = blockIdx.x * 32, r0 = blockIdx.y * 32;
    int x = threadIdx.x, y = threadIdx.y;   // block (32, 8)
    #pragma unroll
    for (int i = 0; i < 32; i += 8) t[y + i][x] = src[(r0 + y + i) * C + c0 + x];
    __syncthreads();
    #pragma unroll
    for (int i = 0; i < 32; i += 8) dst[(c0 + y + i) * R + r0 + x] = t[x][y + i];
}

// ---------------- k-packed A*B^T GEMM, split-K, FFMA2 ----------------
__global__ void __launch_bounds__(256) k_gemm(const float* __restrict__ A,
                                              const float* __restrict__ Bm,
                                              float* __restrict__ out, int ldo,
                                              int kPer) {
    __shared__ float4 As4[64][17];
    __shared__ float4 Bs4[64][17];
    int m0 = blockIdx.x * 64, n0 = blockIdx.y * 64;
    int kBeg = blockIdx.z * kPer;
    int tid = threadIdx.x, tx = tid & 15, ty = tid >> 4;
    const float4* A4 = (const float4*)A;    // row stride 1024 float4
    const float4* B4 = (const float4*)Bm;
    u64 acc[4][4] = {};
    for (int k0 = kBeg; k0 < kBeg + kPer; k0 += 64) {
        __syncthreads();
        #pragma unroll
        for (int s = 0; s < 4; s++) {
            int idx = tid + s * 256;
            int r = idx >> 4, c = idx & 15;
            As4[r][c] = A4[(m0 + r) * 1024 + (k0 >> 2) + c];
            Bs4[r][c] = B4[(n0 + r) * 1024 + (k0 >> 2) + c];
        }
        __syncthreads();
        #pragma unroll
        for (int k4 = 0; k4 < 16; k4++) {
            F4U a[4], b[4];
            #pragma unroll
            for (int ii = 0; ii < 4; ii++) a[ii].f = As4[ty + 16 * ii][k4];
            #pragma unroll
            for (int jj = 0; jj < 4; jj++) b[jj].f = Bs4[tx + 16 * jj][k4];
            #pragma unroll
            for (int ii = 0; ii < 4; ii++)
                #pragma unroll
                for (int jj = 0; jj < 4; jj++) {
                    fma2(acc[ii][jj], a[ii].u[0], b[jj].u[0]);
                    fma2(acc[ii][jj], a[ii].u[1], b[jj].u[1]);
                }
        }
    }
    #pragma unroll
    for (int ii = 0; ii < 4; ii++)
        #pragma unroll
        for (int jj = 0; jj < 4; jj++)
            atomicAdd(&out[(m0 + ty + 16 * ii) * ldo + (n0 + tx + 16 * jj)],
                      upsum(acc[ii][jj]));
}

// ---------------- T^T T upper-triangle tiles ----------------
__global__ void __launch_bounds__(256) k_gemm_tri(int kPer) {
    __shared__ float4 As4[64][17];
    __shared__ float4 Bs4[64][17];
    int t = blockIdx.x, tm = 0;
    while (t >= 12 - tm) { t -= 12 - tm; tm++; }
    int tn = tm + t;
    int m0 = tm * 64, n0 = tn * 64;
    int kBeg = blockIdx.z * kPer;
    int tid = threadIdx.x, tx = tid & 15, ty = tid >> 4;
    const float4* A4 = (const float4*)g_Tt;
    u64 acc[4][4] = {};
    for (int k0 = kBeg; k0 < kBeg + kPer; k0 += 64) {
        __syncthreads();
        #pragma unroll
        for (int s = 0; s < 4; s++) {
            int idx = tid + s * 256;
            int r = idx >> 4, c = idx & 15;
            As4[r][c] = A4[(m0 + r) * 1024 + (k0 >> 2) + c];
            Bs4[r][c] = A4[(n0 + r) * 1024 + (k0 >> 2) + c];
        }
        __syncthreads();
        #pragma unroll
        for (int k4 = 0; k4 < 16; k4++) {
            F4U a[4], b[4];
            #pragma unroll
            for (int ii = 0; ii < 4; ii++) a[ii].f = As4[ty + 16 * ii][k4];
            #pragma unroll
            for (int jj = 0; jj < 4; jj++) b[jj].f = Bs4[tx + 16 * jj][k4];
            #pragma unroll
            for (int ii = 0; ii < 4; ii++)
                #pragma unroll
                for (int jj = 0; jj < 4; jj++) {
                    fma2(acc[ii][jj], a[ii].u[0], b[jj].u[0]);
                    fma2(acc[ii][jj], a[ii].u[1], b[jj].u[1]);
                }
        }
    }
    #pragma unroll
    for (int ii = 0; ii < 4; ii++)
        #pragma unroll
        for (int jj = 0; jj < 4; jj++)
            atomicAdd(&g_TT[(m0 + ty + 16 * ii) * TDIM + (n0 + tx + 16 * jj)],
                      upsum(acc[ii][jj]));
}

// ---------------- distill square-reduce ----------------
__global__ void k_sq3() {
    int i = blockIdx.x * 256 + threadIdx.x;
    int n = gridDim.x * 256;
    float s = 0.f;
    for (int j = i; j < HD * HD; j += n) {
        float v = g_GH[j]; s += v * v * (1.f / (128.f * 128.f));
    }
    for (int j = i; j < HD * TDIM; j += n) {
        float v = g_C[j]; s -= 2.f * v * v * (1.f / 128.f);
    }
    for (int j = i; j < TDIM * TDIM; j += n) {
        int r = j / TDIM, c = j % TDIM;
        if (c < r) continue;
        float v = g_TT[j];
        s += (c == r) ? v * v : 2.f * v * v;
    }
    #pragma unroll
    for (int o = 16; o >= 1; o >>= 1) s += __shfl_xor_sync(0xffffffffu, s, o);
    __shared__ float red[8];
    if ((threadIdx.x & 31) == 0) red[threadIdx.x >> 5] = s;
    __syncthreads();
    if (threadIdx.x == 0) {
        float tot = 0.f;
        #pragma unroll
        for (int k = 0; k < 8; k++) tot += red[k];
        atomicAdd(&g_ST, tot / ((float)BSZ * (float)BSZ));
    }
}

// ---------------- contrastive: SYMMETRIC upper-triangle tiles ----------------
// Tile (i0, j0) with j0 >= i0. Off-diagonal tiles contribute both orientations:
// rows i (mask[i][j]) and cols j (mask[j][i]); exp value shared (sim symmetric).
__global__ void __launch_bounds__(256) k_cont(const int* __restrict__ pmask) {
    __shared__ float4 As4[64][17];
    __shared__ float4 Bs4[64][17];
    __shared__ float sCd[64], sCp[64], sCc[64];
    int i0 = blockIdx.x * 64, j0 = blockIdx.y * 64;
    if (j0 < i0) return;                      // uniform per block
    bool diag = (i0 == j0);
    int tid = threadIdx.x;
    int tx = tid & 15, ty = tid >> 4;
    if (tid < 64) { sCd[tid] = 0.f; sCp[tid] = 0.f; sCc[tid] = 0.f; }
    const float4* LN4 = (const float4*)g_LN;   // row stride = 32 float4

    u64 acc[4][4] = {};
    #pragma unroll
    for (int kh = 0; kh < 2; kh++) {
        __syncthreads();
        #pragma unroll
        for (int s = 0; s < 4; s++) {
            int idx = tid + s * 256;
            int r = idx >> 4, c = idx & 15;
            As4[r][c] = LN4[(i0 + r) * 32 + kh * 16 + c];
            Bs4[r][c] = LN4[(j0 + r) * 32 + kh * 16 + c];
        }
        __syncthreads();
        #pragma unroll
        for (int k4 = 0; k4 < 16; k4++) {
            F4U a[4], b[4];
            #pragma unroll
            for (int ii = 0; ii < 4; ii++) a[ii].f = As4[ty + 16 * ii][k4];
            #pragma unroll
            for (int jj = 0; jj < 4; jj++) b[jj].f = Bs4[tx + 16 * jj][k4];
            #pragma unroll
            for (int ii = 0; ii < 4; ii++)
                #pragma unroll
                for (int jj = 0; jj < 4; jj++) {
                    fma2(acc[ii][jj], a[ii].u[0], b[jj].u[0]);
                    fma2(acc[ii][jj], a[ii].u[1], b[jj].u[1]);
                }
        }
    }

    // epilogue
    float dR[4] = {}, pR[4] = {}, cR[4] = {};
    float dC[4] = {}, pC[4] = {}, cC[4] = {};
    #pragma unroll
    for (int ii = 0; ii < 4; ii++) {
        int gi = i0 + ty + 16 * ii;
        #pragma unroll
        for (int jj = 0; jj < 4; jj++) {
            int gj = j0 + tx + 16 * jj;
            float sv = upsum(acc[ii][jj]) * 5.0f;   // 1/TEMPERATURE
            float e = __expf(sv);
            if (gj != gi) dR[ii] += e;
            if (pmask[gi * BSZ + gj] != 0) { pR[ii] += sv; cR[ii] += 1.0f; }
            if (!diag) {
                dC[jj] += e;                        // gi != gj guaranteed
                if (pmask[gj * BSZ + gi] != 0) { pC[jj] += sv; cC[jj] += 1.0f; }
            }
        }
    }
    // row reduce across tx (lane-minor, width 16)
    #pragma unroll
    for (int ii = 0; ii < 4; ii++) {
        #pragma unroll
        for (int o = 8; o >= 1; o >>= 1) {
            dR[ii] += __shfl_down_sync(0xffffffffu, dR[ii], o, 16);
            pR[ii] += __shfl_down_sync(0xffffffffu, pR[ii], o, 16);
            cR[ii] += __shfl_down_sync(0xffffffffu, cR[ii], o, 16);
        }
    }
    if (tx == 0) {
        #pragma unroll
        for (int ii = 0; ii < 4; ii++) {
            int gi = i0 + ty + 16 * ii;
            atomicAdd(&g_denom[gi], dR[ii]);
            atomicAdd(&g_pos[gi],   pR[ii]);
            atomicAdd(&g_cnt[gi],   cR[ii]);
        }
    }
    if (!diag) {
        // col reduce: combine the two ty rows inside each warp, then smem
        #pragma unroll
        for (int jj = 0; jj < 4; jj++) {
            dC[jj] += __shfl_xor_sync(0xffffffffu, dC[jj], 16);
            pC[jj] += __shfl_xor_sync(0xffffffffu, pC[jj], 16);
            cC[jj] += __shfl_xor_sync(0xffffffffu, cC[jj], 16);
        }
        if ((tid & 16) == 0) {
            #pragma unroll
            for (int jj = 0; jj < 4; jj++) {
                int c = tx + 16 * jj;
                atomicAdd(&sCd[c], dC[jj]);
                atomicAdd(&sCp[c], pC[jj]);
                atomicAdd(&sCc[c], cC[jj]);
            }
        }
        __syncthreads();
        if (tid < 64) {
            atomicAdd(&g_denom[j0 + tid], sCd[tid]);
            atomicAdd(&g_pos[j0 + tid],   sCp[tid]);
            atomicAdd(&g_cnt[j0 + tid],   sCc[tid]);
        }
    }
}

// ---------------- final combine ----------------
__global__ void k_combine(float* __restrict__ out) {
    int tid = threadIdx.x;               // 256 threads
    float cont = 0.f;
    for (int i = tid; i < BSZ; i += 256)
        cont += logf(g_denom[i]) - g_pos[i] / fmaxf(g_cnt[i], 1.0f);
    #pragma unroll
    for (int o = 16; o >= 1; o >>= 1)
        cont += __shfl_xor_sync(0xffffffffu, cont, o);
    __shared__ float r0[8];
    if ((tid & 31) == 0) r0[tid >> 5] = cont;
    __syncthreads();
    if (tid == 0) {
        float cT = 0.f;
        #pragma unroll
        for (int i = 0; i < 8; i++) cT += r0[i];
        float quant = g_quant / ((float)BSZ * (float)HD);
        out[0] = cT / (float)BSZ + 0.5f * g_ST + 0.01f * quant;
    }
}

// ---------------- launch ----------------
extern "C" void kernel_launch(void* const* d_in, const int* in_sizes, int n_in,
                              void* d_out, int out_size) {
    const float* logits = (const float*)d_in[0];
    const float* hash   = (const float*)d_in[1];
    const float* teach  = (const float*)d_in[2];
    const int*   pmask  = (const int*)d_in[3];
    float* out = (float*)d_out;

    float* p_T;  cudaGetSymbolAddress((void**)&p_T,  g_T);
    float* p_Ht; cudaGetSymbolAddress((void**)&p_Ht, g_Ht);
    float* p_Tt; cudaGetSymbolAddress((void**)&p_Tt, g_Tt);
    float* p_GH; cudaGetSymbolAddress((void**)&p_GH, g_GH);
    float* p_C;  cudaGetSymbolAddress((void**)&p_C,  g_C);

    k_zero<<<512, 256>>>();
    k_norm_logits<<<BSZ, 128>>>(logits);
    k_norm_teacher<<<BSZ, 256>>>(teach);
    k_transpose<<<dim3(HD / 32, BSZ / 32), dim3(32, 8)>>>(hash, p_Ht, BSZ, HD);
    k_transpose<<<dim3(TDIM / 32, BSZ / 32), dim3(32, 8)>>>(p_T, p_Tt, BSZ, TDIM);
    // G_H = H^T H : 128x128, split-K 32
    k_gemm<<<dim3(2, 2, 32), 256>>>(p_Ht, p_Ht, p_GH, HD, 128);
    // C = H^T T : 128x768, split-K 16
    k_gemm<<<dim3(2, 12, 16), 256>>>(p_Ht, p_Tt, p_C, TDIM, 256);
    // T^T T upper triangle : 78 tiles, split-K 8
    k_gemm_tri<<<dim3(78, 1, 8), 256>>>(512);
    k_sq3<<<512, 256>>>();
    // contrastive: upper-triangle tiles of the symmetric 4096x4096 sim
    k_cont<<<dim3(64, 64), 256>>>(pmask);
    k_combine<<<1, 256>>>(out);
}

// round 4
// speedup vs baseline: 2.8102x; 1.7025x over previous
#include <cuda_runtime.h>
#include <math.h>

#define BSZ 4096
#define HD  128
#define TDIM 768

// ---------------- device scratch ----------------
__device__ float g_LN[BSZ * HD];        // normalized logits  [B][128]
__device__ float g_T [BSZ * TDIM];      // normalized teacher [B][768]
__device__ float g_Ht[HD * BSZ];        // hash^T   [128][4096]
__device__ float g_Tt[TDIM * BSZ];      // teacher^T [768][4096]
__device__ float g_GH[HD * HD];         // H^T H
__device__ float g_C [HD * TDIM];       // H^T T
__device__ float g_TT[TDIM * TDIM];     // T^T T (upper triangle valid)
__device__ float g_denom[BSZ];
__device__ float g_pos[BSZ];
__device__ float g_cnt[BSZ];
__device__ float g_quant;
__device__ float g_ST;

__device__ __forceinline__ void mma_tf32(float* d, const unsigned* a, const unsigned* b) {
    asm volatile(
        "mma.sync.aligned.m16n8k8.row.col.f32.tf32.tf32.f32 "
        "{%0,%1,%2,%3}, {%4,%5,%6,%7}, {%8,%9}, {%0,%1,%2,%3};"
        : "+f"(d[0]), "+f"(d[1]), "+f"(d[2]), "+f"(d[3])
        : "r"(a[0]), "r"(a[1]), "r"(a[2]), "r"(a[3]), "r"(b[0]), "r"(b[1]));
}

// ---------------- zero accumulators ----------------
__global__ void k_zero() {
    int i = blockIdx.x * 256 + threadIdx.x;
    int n = gridDim.x * 256;
    for (int j = i; j < TDIM * TDIM; j += n) g_TT[j] = 0.f;
    for (int j = i; j < HD * TDIM;  j += n) g_C[j]  = 0.f;
    if (i < HD * HD) g_GH[i] = 0.f;
    if (i < BSZ) { g_denom[i] = 0.f; g_pos[i] = 0.f; g_cnt[i] = 0.f; }
    if (i == 0) { g_quant = 0.f; g_ST = 0.f; }
}

// ---------------- normalize logits + quant partial ----------------
__global__ void k_norm_logits(const float* __restrict__ x) {
    int row = blockIdx.x;
    int t = threadIdx.x;                 // 128 threads
    float v = x[row * HD + t];
    float ss = v * v;
    float q = fabsf(fabsf(v) - 1.0f);
    #pragma unroll
    for (int o = 16; o >= 1; o >>= 1) {
        ss += __shfl_xor_sync(0xffffffffu, ss, o);
        q  += __shfl_xor_sync(0xffffffffu, q, o);
    }
    __shared__ float sred[4], qred[4];
    __shared__ float sinv;
    int w = t >> 5, l = t & 31;
    if (l == 0) { sred[w] = ss; qred[w] = q; }
    __syncthreads();
    if (t == 0) {
        float tot = sred[0] + sred[1] + sred[2] + sred[3];
        float qt  = qred[0] + qred[1] + qred[2] + qred[3];
        atomicAdd(&g_quant, qt);
        sinv = 1.0f / fmaxf(sqrtf(tot), 1e-12f);
    }
    __syncthreads();
    g_LN[row * HD + t] = v * sinv;
}

// ---------------- normalize teacher ----------------
__global__ void k_norm_teacher(const float* __restrict__ x) {
    int row = blockIdx.x;
    int t = threadIdx.x;                 // 256 threads
    float v0 = x[row * TDIM + t];
    float v1 = x[row * TDIM + 256 + t];
    float v2 = x[row * TDIM + 512 + t];
    float ss = v0 * v0 + v1 * v1 + v2 * v2;
    #pragma unroll
    for (int o = 16; o >= 1; o >>= 1) ss += __shfl_xor_sync(0xffffffffu, ss, o);
    __shared__ float sred[8];
    __shared__ float sinv;
    if ((t & 31) == 0) sred[t >> 5] = ss;
    __syncthreads();
    if (t == 0) {
        float tot = 0.f;
        #pragma unroll
        for (int i = 0; i < 8; i++) tot += sred[i];
        sinv = 1.0f / fmaxf(sqrtf(tot), 1e-12f);
    }
    __syncthreads();
    g_T[row * TDIM + t]       = v0 * sinv;
    g_T[row * TDIM + 256 + t] = v1 * sinv;
    g_T[row * TDIM + 512 + t] = v2 * sinv;
}

// ---------------- tiled transpose ----------------
__global__ void k_transpose(const float* __restrict__ src, float* __restrict__ dst,
                            int R, int C) {
    __shared__ float t[32][33];
    int c0 = blockIdx.x * 32, r0 = blockIdx.y * 32;
    int x = threadIdx.x, y = threadIdx.y;   // block (32, 8)
    #pragma unroll
    for (int i = 0; i < 32; i += 8) t[y + i][x] = src[(r0 + y + i) * C + c0 + x];
    __syncthreads();
    #pragma unroll
    for (int i = 0; i < 32; i += 8) dst[(c0 + y + i) * R + r0 + x] = t[x][y + i];
}

// ======== mma tile core helpers ========
// smem tiles: unsigned [64][68]; pad 68 -> bank = (4r + c) conflict-free
// warp layout: 8 warps = 2(m) x 4(n); warp tile 32x16; frags 2(mi) x 2(ni)

#define LOAD_TILES(A4src, B4src)                                           \
    do {                                                                    \
        _Pragma("unroll")                                                   \
        for (int s = 0; s < 4; s++) {                                       \
            int idx = tid + s * 256;                                        \
            int r = idx >> 4, c16 = idx & 15;                               \
            *(float4*)&As[r][c16 * 4] = (A4src);                            \
            *(float4*)&Bs[r][c16 * 4] = (B4src);                            \
        }                                                                   \
    } while (0)

#define MMA_CHUNK()                                                         \
    do {                                                                    \
        _Pragma("unroll")                                                   \
        for (int kk = 0; kk < 8; kk++) {                                    \
            int kb = kk * 8;                                                \
            unsigned af[2][4], bf[2][2];                                    \
            _Pragma("unroll")                                               \
            for (int mi = 0; mi < 2; mi++) {                                \
                int rr = wm * 32 + mi * 16 + fr;                            \
                af[mi][0] = As[rr][kb + fc];                                \
                af[mi][1] = As[rr + 8][kb + fc];                            \
                af[mi][2] = As[rr][kb + fc + 4];                            \
                af[mi][3] = As[rr + 8][kb + fc + 4];                        \
            }                                                               \
            _Pragma("unroll")                                               \
            for (int ni = 0; ni < 2; ni++) {                                \
                int rn = wn * 16 + ni * 8 + fr;                             \
                bf[ni][0] = Bs[rn][kb + fc];                                \
                bf[ni][1] = Bs[rn][kb + fc + 4];                            \
            }                                                               \
            _Pragma("unroll")                                               \
            for (int mi = 0; mi < 2; mi++)                                  \
                _Pragma("unroll")                                           \
                for (int ni = 0; ni < 2; ni++)                              \
                    mma_tf32(acc[mi][ni], af[mi], bf[ni]);                  \
        }                                                                   \
    } while (0)

// ---------------- generic A*B^T GEMM (k-contig operands), split-K ----------
__global__ void __launch_bounds__(256) k_gemm(const float* __restrict__ A,
                                              const float* __restrict__ Bm,
                                              float* __restrict__ out, int ldo,
                                              int kPer) {
    __shared__ __align__(16) unsigned As[64][68];
    __shared__ __align__(16) unsigned Bs[64][68];
    int m0 = blockIdx.x * 64, n0 = blockIdx.y * 64;
    int kBeg = blockIdx.z * kPer;
    int tid = threadIdx.x, lane = tid & 31, w = tid >> 5;
    int wm = w & 1, wn = w >> 1;
    int fr = lane >> 2, fc = lane & 3;
    const float4* A4 = (const float4*)A;    // row stride 1024 float4
    const float4* B4 = (const float4*)Bm;
    float acc[2][2][4] = {};
    for (int k0 = kBeg; k0 < kBeg + kPer; k0 += 64) {
        __syncthreads();
        LOAD_TILES(A4[(m0 + r) * 1024 + (k0 >> 2) + c16],
                   B4[(n0 + r) * 1024 + (k0 >> 2) + c16]);
        __syncthreads();
        MMA_CHUNK();
    }
    #pragma unroll
    for (int mi = 0; mi < 2; mi++)
        #pragma unroll
        for (int ni = 0; ni < 2; ni++)
            #pragma unroll
            for (int h = 0; h < 2; h++)
                #pragma unroll
                for (int q = 0; q < 2; q++) {
                    int gi = m0 + wm * 32 + mi * 16 + fr + h * 8;
                    int gj = n0 + wn * 16 + ni * 8 + fc * 2 + q;
                    atomicAdd(&out[gi * ldo + gj], acc[mi][ni][h * 2 + q]);
                }
}

// ---------------- T^T T upper-triangle tiles ----------------
__global__ void __launch_bounds__(256) k_gemm_tri(int kPer) {
    __shared__ __align__(16) unsigned As[64][68];
    __shared__ __align__(16) unsigned Bs[64][68];
    int t = blockIdx.x, tm = 0;
    while (t >= 12 - tm) { t -= 12 - tm; tm++; }
    int tn = tm + t;
    int m0 = tm * 64, n0 = tn * 64;
    int kBeg = blockIdx.z * kPer;
    int tid = threadIdx.x, lane = tid & 31, w = tid >> 5;
    int wm = w & 1, wn = w >> 1;
    int fr = lane >> 2, fc = lane & 3;
    const float4* A4 = (const float4*)g_Tt;
    float acc[2][2][4] = {};
    for (int k0 = kBeg; k0 < kBeg + kPer; k0 += 64) {
        __syncthreads();
        LOAD_TILES(A4[(m0 + r) * 1024 + (k0 >> 2) + c16],
                   A4[(n0 + r) * 1024 + (k0 >> 2) + c16]);
        __syncthreads();
        MMA_CHUNK();
    }
    #pragma unroll
    for (int mi = 0; mi < 2; mi++)
        #pragma unroll
        for (int ni = 0; ni < 2; ni++)
            #pragma unroll
            for (int h = 0; h < 2; h++)
                #pragma unroll
                for (int q = 0; q < 2; q++) {
                    int gi = m0 + wm * 32 + mi * 16 + fr + h * 8;
                    int gj = n0 + wn * 16 + ni * 8 + fc * 2 + q;
                    atomicAdd(&g_TT[gi * TDIM + gj], acc[mi][ni][h * 2 + q]);
                }
}

// ---------------- distill square-reduce ----------------
__global__ void k_sq3() {
    int i = blockIdx.x * 256 + threadIdx.x;
    int n = gridDim.x * 256;
    float s = 0.f;
    for (int j = i; j < HD * HD; j += n) {
        float v = g_GH[j]; s += v * v * (1.f / (128.f * 128.f));
    }
    for (int j = i; j < HD * TDIM; j += n) {
        float v = g_C[j]; s -= 2.f * v * v * (1.f / 128.f);
    }
    for (int j = i; j < TDIM * TDIM; j += n) {
        int r = j / TDIM, c = j % TDIM;
        if (c < r) continue;
        float v = g_TT[j];
        s += (c == r) ? v * v : 2.f * v * v;
    }
    #pragma unroll
    for (int o = 16; o >= 1; o >>= 1) s += __shfl_xor_sync(0xffffffffu, s, o);
    __shared__ float red[8];
    if ((threadIdx.x & 31) == 0) red[threadIdx.x >> 5] = s;
    __syncthreads();
    if (threadIdx.x == 0) {
        float tot = 0.f;
        #pragma unroll
        for (int k = 0; k < 8; k++) tot += red[k];
        atomicAdd(&g_ST, tot / ((float)BSZ * (float)BSZ));
    }
}

// ---------------- contrastive: symmetric upper-triangle tiles, mma core ------
__global__ void __launch_bounds__(256) k_cont(const int* __restrict__ pmask) {
    __shared__ __align__(16) unsigned As[64][68];
    __shared__ __align__(16) unsigned Bs[64][68];
    __shared__ float sRd[64], sRp[64], sRc[64];
    __shared__ float sCd[64], sCp[64], sCc[64];
    int i0 = blockIdx.x * 64, j0 = blockIdx.y * 64;
    if (j0 < i0) return;
    bool diag = (i0 == j0);
    int tid = threadIdx.x, lane = tid & 31, w = tid >> 5;
    int wm = w & 1, wn = w >> 1;
    int fr = lane >> 2, fc = lane & 3;
    if (tid < 64) {
        sRd[tid] = 0.f; sRp[tid] = 0.f; sRc[tid] = 0.f;
        sCd[tid] = 0.f; sCp[tid] = 0.f; sCc[tid] = 0.f;
    }
    const float4* LN4 = (const float4*)g_LN;   // row stride = 32 float4
    float acc[2][2][4] = {};
    #pragma unroll
    for (int kc = 0; kc < 2; kc++) {
        __syncthreads();
        LOAD_TILES(LN4[(i0 + r) * 32 + kc * 16 + c16],
                   LN4[(j0 + r) * 32 + kc * 16 + c16]);
        __syncthreads();
        MMA_CHUNK();
    }

    // ---- epilogue: exp/denom + masked pos (both orientations) ----
    float dR[2][2] = {}, pR[2][2] = {}, cR[2][2] = {};
    float dC[2][2] = {}, pC[2][2] = {}, cC[2][2] = {};
    #pragma unroll
    for (int mi = 0; mi < 2; mi++)
        #pragma unroll
        for (int ni = 0; ni < 2; ni++)
            #pragma unroll
            for (int h = 0; h < 2; h++)
                #pragma unroll
                for (int q = 0; q < 2; q++) {
                    int gi = i0 + wm * 32 + mi * 16 + fr + h * 8;
                    int gj = j0 + wn * 16 + ni * 8 + fc * 2 + q;
                    float sv = acc[mi][ni][h * 2 + q] * 5.0f;  // 1/TEMPERATURE
                    float e = __expf(sv);
                    if (gj != gi) dR[mi][h] += e;
                    if (pmask[gi * BSZ + gj] != 0) { pR[mi][h] += sv; cR[mi][h] += 1.0f; }
                    if (!diag) {
                        dC[ni][q] += e;
                        if (pmask[gj * BSZ + gi] != 0) { pC[ni][q] += sv; cC[ni][q] += 1.0f; }
                    }
                }
    // row reduce over fc lanes (width 4)
    #pragma unroll
    for (int mi = 0; mi < 2; mi++)
        #pragma unroll
        for (int h = 0; h < 2; h++) {
            #pragma unroll
            for (int o = 2; o >= 1; o >>= 1) {
                dR[mi][h] += __shfl_down_sync(0xffffffffu, dR[mi][h], o, 4);
                pR[mi][h] += __shfl_down_sync(0xffffffffu, pR[mi][h], o, 4);
                cR[mi][h] += __shfl_down_sync(0xffffffffu, cR[mi][h], o, 4);
            }
            if (fc == 0) {
                int lr = wm * 32 + mi * 16 + fr + h * 8;
                atomicAdd(&sRd[lr], dR[mi][h]);
                atomicAdd(&sRp[lr], pR[mi][h]);
                atomicAdd(&sRc[lr], cR[mi][h]);
            }
        }
    // col reduce over fr lanes (xor 4, 8, 16)
    if (!diag) {
        #pragma unroll
        for (int ni = 0; ni < 2; ni++)
            #pragma unroll
            for (int q = 0; q < 2; q++) {
                #pragma unroll
                for (int o = 16; o >= 4; o >>= 1) {
                    dC[ni][q] += __shfl_xor_sync(0xffffffffu, dC[ni][q], o);
                    pC[ni][q] += __shfl_xor_sync(0xffffffffu, pC[ni][q], o);
                    cC[ni][q] += __shfl_xor_sync(0xffffffffu, cC[ni][q], o);
                }
                if (fr == 0) {
                    int lc = wn * 16 + ni * 8 + fc * 2 + q;
                    atomicAdd(&sCd[lc], dC[ni][q]);
                    atomicAdd(&sCp[lc], pC[ni][q]);
                    atomicAdd(&sCc[lc], cC[ni][q]);
                }
            }
    }
    __syncthreads();
    if (tid < 64) {
        atomicAdd(&g_denom[i0 + tid], sRd[tid]);
        atomicAdd(&g_pos[i0 + tid],   sRp[tid]);
        atomicAdd(&g_cnt[i0 + tid],   sRc[tid]);
        if (!diag) {
            atomicAdd(&g_denom[j0 + tid], sCd[tid]);
            atomicAdd(&g_pos[j0 + tid],   sCp[tid]);
            atomicAdd(&g_cnt[j0 + tid],   sCc[tid]);
        }
    }
}

// ---------------- final combine ----------------
__global__ void k_combine(float* __restrict__ out) {
    int tid = threadIdx.x;               // 256 threads
    float cont = 0.f;
    for (int i = tid; i < BSZ; i += 256)
        cont += logf(g_denom[i]) - g_pos[i] / fmaxf(g_cnt[i], 1.0f);
    #pragma unroll
    for (int o = 16; o >= 1; o >>= 1)
        cont += __shfl_xor_sync(0xffffffffu, cont, o);
    __shared__ float r0[8];
    if ((tid & 31) == 0) r0[tid >> 5] = cont;
    __syncthreads();
    if (tid == 0) {
        float cT = 0.f;
        #pragma unroll
        for (int i = 0; i < 8; i++) cT += r0[i];
        float quant = g_quant / ((float)BSZ * (float)HD);
        out[0] = cT / (float)BSZ + 0.5f * g_ST + 0.01f * quant;
    }
}

// ---------------- launch ----------------
extern "C" void kernel_launch(void* const* d_in, const int* in_sizes, int n_in,
                              void* d_out, int out_size) {
    const float* logits = (const float*)d_in[0];
    const float* hash   = (const float*)d_in[1];
    const float* teach  = (const float*)d_in[2];
    const int*   pmask  = (const int*)d_in[3];
    float* out = (float*)d_out;

    float* p_T;  cudaGetSymbolAddress((void**)&p_T,  g_T);
    float* p_Ht; cudaGetSymbolAddress((void**)&p_Ht, g_Ht);
    float* p_Tt; cudaGetSymbolAddress((void**)&p_Tt, g_Tt);
    float* p_GH; cudaGetSymbolAddress((void**)&p_GH, g_GH);
    float* p_C;  cudaGetSymbolAddress((void**)&p_C,  g_C);

    k_zero<<<512, 256>>>();
    k_norm_logits<<<BSZ, 128>>>(logits);
    k_norm_teacher<<<BSZ, 256>>>(teach);
    k_transpose<<<dim3(HD / 32, BSZ / 32), dim3(32, 8)>>>(hash, p_Ht, BSZ, HD);
    k_transpose<<<dim3(TDIM / 32, BSZ / 32), dim3(32, 8)>>>(p_T, p_Tt, BSZ, TDIM);
    // G_H = H^T H : 128x128, split-K 32
    k_gemm<<<dim3(2, 2, 32), 256>>>(p_Ht, p_Ht, p_GH, HD, 128);
    // C = H^T T : 128x768, split-K 16
    k_gemm<<<dim3(2, 12, 16), 256>>>(p_Ht, p_Tt, p_C, TDIM, 256);
    // T^T T upper triangle : 78 tiles, split-K 8
    k_gemm_tri<<<dim3(78, 1, 8), 256>>>(512);
    k_sq3<<<512, 256>>>();
    // contrastive: upper-triangle tiles of the symmetric 4096x4096 sim
    k_cont<<<dim3(64, 64), 256>>>(pmask);
    k_combine<<<1, 256>>>(out);
}